// round 1
// baseline (speedup 1.0000x reference)
#include <cuda_runtime.h>
#include <cuda_bf16.h>
#include <cstdint>

// Problem constants
#define BB 2
#define SS 2048
#define HID 4096
#define NH 32
#define NKV 8
#define HD 128
#define TOK (BB*SS)            // 4096 tokens
#define SCALING 0.08838834764831845f
#define NEG_BIG -1e9f

// ---------------- scratch (allocation-free: __device__ globals) ----------------
__device__ float g_q[(size_t)TOK * (NH * HD)];     // 64 MB  [t][h*128+d]
__device__ float g_k[(size_t)TOK * (NKV * HD)];    // 16 MB  [t][kvh*128+d]
__device__ float g_kt[(size_t)BB * NKV * HD * SS]; // 16 MB  [(b*8+kvh)][d][s]
__device__ float g_v[(size_t)TOK * (NKV * HD)];    // 16 MB  [t][kvh*128+d]
__device__ float g_attn[(size_t)TOK * (NH * HD)];  // 64 MB  [t][h*128+d]

// ---------------- SGEMM: C[M,N] = A[M,K] * B[K,N], all row-major ----------------
// BM=BN=128, BK=16, 256 threads, 8x8 per thread, float4 everywhere.
#define GBM 128
#define GBN 128
#define GBK 16

__global__ __launch_bounds__(256) void sgemm128(
    const float* __restrict__ A, const float* __restrict__ B,
    float* __restrict__ C, int M, int N, int K)
{
    __shared__ float As[GBK][GBM];   // stored transposed: As[k][m]
    __shared__ float Bs[GBK][GBN];

    const int tid = threadIdx.x;
    const int bx = blockIdx.x;       // N tile
    const int by = blockIdx.y;       // M tile
    const int tx = tid & 15;
    const int ty = tid >> 4;

    const int aRow = tid >> 2;          // 0..63 (+64 for second)
    const int aCol = (tid & 3) << 2;    // 0,4,8,12
    const int bRow = tid >> 5;          // 0..7 (+8 for second)
    const int bCol = (tid & 31) << 2;   // 0..124

    const float* Aptr = A + (size_t)by * GBM * K;
    const float* Bptr = B + (size_t)bx * GBN;

    float acc[8][8];
#pragma unroll
    for (int i = 0; i < 8; i++)
#pragma unroll
        for (int j = 0; j < 8; j++) acc[i][j] = 0.f;

    for (int kt = 0; kt < K; kt += GBK) {
#pragma unroll
        for (int u = 0; u < 2; u++) {
            int r = aRow + u * 64;
            float4 v = *(const float4*)(Aptr + (size_t)r * K + kt + aCol);
            As[aCol + 0][r] = v.x;
            As[aCol + 1][r] = v.y;
            As[aCol + 2][r] = v.z;
            As[aCol + 3][r] = v.w;
        }
#pragma unroll
        for (int u = 0; u < 2; u++) {
            int r = bRow + u * 8;
            *(float4*)&Bs[r][bCol] = *(const float4*)(Bptr + (size_t)(kt + r) * N + bCol);
        }
        __syncthreads();

#pragma unroll
        for (int k = 0; k < GBK; k++) {
            float4 a0 = *(float4*)&As[k][ty * 8];
            float4 a1 = *(float4*)&As[k][ty * 8 + 4];
            float4 b0 = *(float4*)&Bs[k][tx * 8];
            float4 b1 = *(float4*)&Bs[k][tx * 8 + 4];
            float ra[8] = {a0.x,a0.y,a0.z,a0.w,a1.x,a1.y,a1.z,a1.w};
            float rb[8] = {b0.x,b0.y,b0.z,b0.w,b1.x,b1.y,b1.z,b1.w};
#pragma unroll
            for (int i = 0; i < 8; i++)
#pragma unroll
                for (int j = 0; j < 8; j++)
                    acc[i][j] += ra[i] * rb[j];
        }
        __syncthreads();
    }

    float* Cptr = C + (size_t)(by * GBM) * N + bx * GBN;
#pragma unroll
    for (int i = 0; i < 8; i++) {
        float* crow = Cptr + (size_t)(ty * 8 + i) * N + tx * 8;
        float4 o0 = make_float4(acc[i][0], acc[i][1], acc[i][2], acc[i][3]);
        float4 o1 = make_float4(acc[i][4], acc[i][5], acc[i][6], acc[i][7]);
        *(float4*)(crow) = o0;
        *(float4*)(crow + 4) = o1;
    }
}

// ---------------- RoPE on Q (in place) ----------------
// grid: TOK blocks x 256 threads
__global__ __launch_bounds__(256) void rope_q_kernel(
    float* __restrict__ Q, const float* __restrict__ cosp, const float* __restrict__ sinp)
{
    const int t = blockIdx.x;
    float* row = Q + (size_t)t * (NH * HD);
    const float* cr = cosp + (size_t)t * HD;
    const float* sr = sinp + (size_t)t * HD;
    for (int i = threadIdx.x; i < NH * 64; i += 256) {
        int hh = i >> 6, d = i & 63;
        float* p = row + hh * HD;
        float x0 = p[d], x1 = p[d + 64];
        float c0 = cr[d], c1 = cr[d + 64];
        float s0 = sr[d], s1 = sr[d + 64];
        p[d]      = x0 * c0 - x1 * s0;
        p[d + 64] = x1 * c1 + x0 * s1;
    }
}

// ---------------- RoPE on K + transpose to [bkv][d][s] ----------------
// grid: (SS/64, NKV, BB) x 256 threads
__global__ __launch_bounds__(256) void rope_kt_kernel(
    const float* __restrict__ K, const float* __restrict__ cosp,
    const float* __restrict__ sinp, float* __restrict__ Kt)
{
    __shared__ float Ts[128 * 65];
    const int st = blockIdx.x, kvh = blockIdx.y, b = blockIdx.z;
    const int s0 = st * 64;
    const int tid = threadIdx.x;

    for (int i = tid; i < 64 * 64; i += 256) {
        int sl = i >> 6, d = i & 63;
        int t = b * SS + s0 + sl;
        const float* row = K + (size_t)t * (NKV * HD) + kvh * HD;
        float x0 = row[d], x1 = row[d + 64];
        float c0 = cosp[(size_t)t * HD + d], c1 = cosp[(size_t)t * HD + d + 64];
        float n0 = sinp[(size_t)t * HD + d], n1 = sinp[(size_t)t * HD + d + 64];
        Ts[d * 65 + sl]        = x0 * c0 - x1 * n0;
        Ts[(d + 64) * 65 + sl] = x1 * c1 + x0 * n1;
    }
    __syncthreads();
    float* base = Kt + ((size_t)(b * NKV + kvh)) * HD * SS + s0;
    for (int i = tid; i < 128 * 64; i += 256) {
        int d = i >> 6, sl = i & 63;
        base[(size_t)d * SS + sl] = Ts[d * 65 + sl];
    }
}

// ---------------- Flash attention (fp32, causal, online softmax) ----------------
// BQ=128 rows, BK=64 keys, D=128, 512 threads.
#define FA_BQ 128
#define FA_BK 64
#define FA_THREADS 512
// smem floats: Qs 16384 + Ks 8192 + Vs 8192 + Ss 8320 + m/l/rsc 384 + red 512
#define FA_SMEM_FLOATS (16384 + 8192 + 8192 + 8320 + 384 + 512)
#define FA_SMEM_BYTES (FA_SMEM_FLOATS * 4)

__global__ __launch_bounds__(FA_THREADS, 1) void flash_kernel(
    const float* __restrict__ Q, const float* __restrict__ Kt,
    const float* __restrict__ V, float* __restrict__ O)
{
    extern __shared__ float sm[];
    float* Qs   = sm;                  // [128][128]
    float* Ks   = Qs + 128 * 128;      // [128][64]  d-major
    float* Vs   = Ks + 128 * 64;       // [64][128]
    float* Ss   = Vs + 64 * 128;       // [128][65]
    float* rowm = Ss + 128 * 65;       // [128]
    float* rowl = rowm + 128;          // [128]
    float* rsc  = rowl + 128;          // [128]
    float* red  = rsc + 128;           // [4][128]

    const int tid = threadIdx.x;
    const int qt = blockIdx.x, h = blockIdx.y, b = blockIdx.z;
    const int kvh = h >> 2;
    const int q0 = qt * FA_BQ;
    const int tx = tid & 15;
    const int ty = tid >> 4;    // 0..31

    const float* Qbase  = Q  + ((size_t)(b * SS + q0)) * (NH * HD) + h * HD;
    const float* Ktbase = Kt + ((size_t)(b * NKV + kvh)) * HD * SS;
    const float* Vbase  = V  + ((size_t)(b * SS)) * (NKV * HD) + kvh * HD;

    // load Q tile: 128 rows x 128 cols
    for (int i = tid; i < 128 * 32; i += FA_THREADS) {
        int r = i >> 5, c4 = (i & 31) << 2;
        *(float4*)&Qs[r * 128 + c4] = *(const float4*)(Qbase + (size_t)r * (NH * HD) + c4);
    }
    if (tid < 128) { rowm[tid] = -1e30f; rowl[tid] = 0.f; }

    float acc[4][8];
#pragma unroll
    for (int i = 0; i < 4; i++)
#pragma unroll
        for (int j = 0; j < 8; j++) acc[i][j] = 0.f;
    __syncthreads();

    const int ktiles = (q0 + FA_BQ) / FA_BK;   // causal upper bound
    for (int kt = 0; kt < ktiles; kt++) {
        const int k0 = kt * FA_BK;

        // load K tile (d-major): Ks[d][c]
        for (int i = tid; i < 128 * 16; i += FA_THREADS) {
            int d = i >> 4, c4 = (i & 15) << 2;
            *(float4*)&Ks[d * 64 + c4] = *(const float4*)(Ktbase + (size_t)d * SS + k0 + c4);
        }
        // load V tile: Vs[r][c]
        for (int i = tid; i < 64 * 32; i += FA_THREADS) {
            int r = i >> 5, c4 = (i & 31) << 2;
            *(float4*)&Vs[r * 128 + c4] = *(const float4*)(Vbase + (size_t)(k0 + r) * (NKV * HD) + c4);
        }
        __syncthreads();

        // S = Q * K^T : thread patch rows ty*4.., cols tx*4..
        float sacc[4][4];
#pragma unroll
        for (int i = 0; i < 4; i++)
#pragma unroll
            for (int j = 0; j < 4; j++) sacc[i][j] = 0.f;

#pragma unroll 4
        for (int d = 0; d < 128; d++) {
            float4 kb = *(float4*)&Ks[d * 64 + (tx << 2)];
            float qa[4];
#pragma unroll
            for (int i = 0; i < 4; i++) qa[i] = Qs[(ty * 4 + i) * 128 + d];
#pragma unroll
            for (int i = 0; i < 4; i++) {
                sacc[i][0] += qa[i] * kb.x;
                sacc[i][1] += qa[i] * kb.y;
                sacc[i][2] += qa[i] * kb.z;
                sacc[i][3] += qa[i] * kb.w;
            }
        }

        // scale + causal mask, write S tile
#pragma unroll
        for (int i = 0; i < 4; i++) {
            int qi = q0 + ty * 4 + i;
#pragma unroll
            for (int j = 0; j < 4; j++) {
                int kj = k0 + tx * 4 + j;
                float s = sacc[i][j] * SCALING;
                if (kj > qi) s = NEG_BIG;
                Ss[(ty * 4 + i) * 65 + tx * 4 + j] = s;
            }
        }
        __syncthreads();

        // online softmax: 512 threads = 128 rows x 4 segments of 16 cols
        {
            const int r = tid & 127, seg = tid >> 7;
            float pm = -1e30f;
#pragma unroll
            for (int j = 0; j < 16; j++) pm = fmaxf(pm, Ss[r * 65 + seg * 16 + j]);
            red[seg * 128 + r] = pm;
            __syncthreads();
            float mo = rowm[r];
            float mt = fmaxf(fmaxf(red[r], red[128 + r]), fmaxf(red[256 + r], red[384 + r]));
            float mn = fmaxf(mo, mt);
            __syncthreads();
            float ps = 0.f;
#pragma unroll
            for (int j = 0; j < 16; j++) {
                float e = __expf(Ss[r * 65 + seg * 16 + j] - mn);
                Ss[r * 65 + seg * 16 + j] = e;
                ps += e;
            }
            red[seg * 128 + r] = ps;
            __syncthreads();
            if (seg == 0) {
                float l = red[r] + red[128 + r] + red[256 + r] + red[384 + r];
                float sc = __expf(mo - mn);
                rowl[r] = rowl[r] * sc + l;
                rowm[r] = mn;
                rsc[r]  = sc;
            }
            __syncthreads();
        }

        // O = O*rsc + P*V
        float f[4];
#pragma unroll
        for (int i = 0; i < 4; i++) f[i] = rsc[ty * 4 + i];
#pragma unroll
        for (int i = 0; i < 4; i++)
#pragma unroll
            for (int j = 0; j < 8; j++) acc[i][j] *= f[i];

#pragma unroll 2
        for (int k = 0; k < 64; k++) {
            float4 v0 = *(float4*)&Vs[k * 128 + tx * 8];
            float4 v1 = *(float4*)&Vs[k * 128 + tx * 8 + 4];
#pragma unroll
            for (int i = 0; i < 4; i++) {
                float p = Ss[(ty * 4 + i) * 65 + k];
                acc[i][0] += p * v0.x; acc[i][1] += p * v0.y;
                acc[i][2] += p * v0.z; acc[i][3] += p * v0.w;
                acc[i][4] += p * v1.x; acc[i][5] += p * v1.y;
                acc[i][6] += p * v1.z; acc[i][7] += p * v1.w;
            }
        }
        __syncthreads();   // protect Ks/Vs/Ss before next tile's loads
    }

    // epilogue: divide by l, write out
    float* Ob = O + ((size_t)(b * SS + q0)) * (NH * HD) + h * HD;
#pragma unroll
    for (int i = 0; i < 4; i++) {
        float inv = 1.0f / rowl[ty * 4 + i];
        float4 o0 = make_float4(acc[i][0] * inv, acc[i][1] * inv, acc[i][2] * inv, acc[i][3] * inv);
        float4 o1 = make_float4(acc[i][4] * inv, acc[i][5] * inv, acc[i][6] * inv, acc[i][7] * inv);
        float* orow = Ob + (size_t)(ty * 4 + i) * (NH * HD) + tx * 8;
        *(float4*)(orow) = o0;
        *(float4*)(orow + 4) = o1;
    }
}

// ---------------- launch ----------------
extern "C" void kernel_launch(void* const* d_in, const int* in_sizes, int n_in,
                              void* d_out, int out_size)
{
    const float* hs   = (const float*)d_in[0];
    const float* cosp = (const float*)d_in[1];
    const float* sinp = (const float*)d_in[2];
    // d_in[3] attention_mask unused (causal computed directly)
    const float* wq = (const float*)d_in[4];
    const float* wk = (const float*)d_in[5];
    const float* wv = (const float*)d_in[6];
    const float* wo = (const float*)d_in[7];
    float* out = (float*)d_out;

    float *q, *k, *ktp, *v, *attn;
    cudaGetSymbolAddress((void**)&q,    g_q);
    cudaGetSymbolAddress((void**)&k,    g_k);
    cudaGetSymbolAddress((void**)&ktp,  g_kt);
    cudaGetSymbolAddress((void**)&v,    g_v);
    cudaGetSymbolAddress((void**)&attn, g_attn);

    // projections
    sgemm128<<<dim3(NH * HD / GBN, TOK / GBM), 256>>>(hs, wq, q, TOK, NH * HD, HID);
    sgemm128<<<dim3(NKV * HD / GBN, TOK / GBM), 256>>>(hs, wk, k, TOK, NKV * HD, HID);
    sgemm128<<<dim3(NKV * HD / GBN, TOK / GBM), 256>>>(hs, wv, v, TOK, NKV * HD, HID);

    // rope
    rope_q_kernel<<<TOK, 256>>>(q, cosp, sinp);
    rope_kt_kernel<<<dim3(SS / 64, NKV, BB), 256>>>(k, cosp, sinp, ktp);

    // attention
    cudaFuncSetAttribute(flash_kernel, cudaFuncAttributeMaxDynamicSharedMemorySize, FA_SMEM_BYTES);
    flash_kernel<<<dim3(SS / FA_BQ, NH, BB), FA_THREADS, FA_SMEM_BYTES>>>(q, ktp, v, attn);

    // output projection
    sgemm128<<<dim3(HID / GBN, TOK / GBM), 256>>>(attn, wo, out, TOK, HID, HID);
}

// round 3
// speedup vs baseline: 1.8687x; 1.8687x over previous
#include <cuda_runtime.h>
#include <cuda_bf16.h>
#include <cstdint>

// Problem constants
#define BB 2
#define SS 2048
#define HID 4096
#define NH 32
#define NKV 8
#define HD 128
#define TOK (BB*SS)            // 4096 tokens
#define SCALING 0.08838834764831845f
#define NEG_BIG -1e9f

// ---------------- scratch (allocation-free: __device__ globals) ----------------
__device__ float g_q[(size_t)TOK * (NH * HD)];
__device__ float g_k[(size_t)TOK * (NKV * HD)];
__device__ float g_kt[(size_t)BB * NKV * HD * SS]; // [(b*8+kvh)][d][s]
__device__ float g_v[(size_t)TOK * (NKV * HD)];
__device__ float g_attn[(size_t)TOK * (NH * HD)];

// bf16 split buffers
__device__ __nv_bfloat16 g_hs_h[(size_t)TOK * HID];
__device__ __nv_bfloat16 g_hs_l[(size_t)TOK * HID];
__device__ __nv_bfloat16 g_wqt_h[(size_t)(NH*HD) * HID];
__device__ __nv_bfloat16 g_wqt_l[(size_t)(NH*HD) * HID];
__device__ __nv_bfloat16 g_wkt_h[(size_t)(NKV*HD) * HID];
__device__ __nv_bfloat16 g_wkt_l[(size_t)(NKV*HD) * HID];
__device__ __nv_bfloat16 g_wvt_h[(size_t)(NKV*HD) * HID];
__device__ __nv_bfloat16 g_wvt_l[(size_t)(NKV*HD) * HID];
__device__ __nv_bfloat16 g_wot_h[(size_t)HID * (NH*HD)];
__device__ __nv_bfloat16 g_wot_l[(size_t)HID * (NH*HD)];
__device__ __nv_bfloat16 g_at_h[(size_t)TOK * (NH*HD)];
__device__ __nv_bfloat16 g_at_l[(size_t)TOK * (NH*HD)];

// ================= helpers =================
__device__ __forceinline__ uint32_t smem_u32(const void* p) {
    uint32_t a;
    asm("{ .reg .u64 t; cvta.to.shared.u64 t, %1; cvt.u32.u64 %0, t; }" : "=r"(a) : "l"(p));
    return a;
}

#define CP_ASYNC16(dst, src) \
    asm volatile("cp.async.cg.shared.global [%0], [%1], 16;" :: "r"(dst), "l"(src))
#define CP_COMMIT() asm volatile("cp.async.commit_group;")
#define CP_WAIT1()  asm volatile("cp.async.wait_group 1;")
#define CP_WAIT0()  asm volatile("cp.async.wait_group 0;")

#define LDMX4(r0,r1,r2,r3,addr) \
    asm volatile("ldmatrix.sync.aligned.m8n8.x4.shared.b16 {%0,%1,%2,%3}, [%4];" \
        : "=r"(r0),"=r"(r1),"=r"(r2),"=r"(r3) : "r"(addr))
#define LDMX2(r0,r1,addr) \
    asm volatile("ldmatrix.sync.aligned.m8n8.x2.shared.b16 {%0,%1}, [%2];" \
        : "=r"(r0),"=r"(r1) : "r"(addr))
#define MMA16816(c0,c1,c2,c3,a0,a1,a2,a3,b0,b1) \
    asm volatile("mma.sync.aligned.m16n8k16.row.col.f32.bf16.bf16.f32 " \
        "{%0,%1,%2,%3}, {%4,%5,%6,%7}, {%8,%9}, {%0,%1,%2,%3};" \
        : "+f"(c0),"+f"(c1),"+f"(c2),"+f"(c3) \
        : "r"(a0),"r"(a1),"r"(a2),"r"(a3), "r"(b0),"r"(b1))

// ================ prep kernels ================
__global__ __launch_bounds__(256) void conv_split(
    const float* __restrict__ X, __nv_bfloat16* __restrict__ H,
    __nv_bfloat16* __restrict__ L, int n4)
{
    int i = blockIdx.x * 256 + threadIdx.x;
    if (i >= n4) return;
    float4 v = ((const float4*)X)[i];
    __nv_bfloat16 h0 = __float2bfloat16(v.x), h1 = __float2bfloat16(v.y);
    __nv_bfloat16 h2 = __float2bfloat16(v.z), h3 = __float2bfloat16(v.w);
    __nv_bfloat16 l0 = __float2bfloat16(v.x - __bfloat162float(h0));
    __nv_bfloat16 l1 = __float2bfloat16(v.y - __bfloat162float(h1));
    __nv_bfloat16 l2 = __float2bfloat16(v.z - __bfloat162float(h2));
    __nv_bfloat16 l3 = __float2bfloat16(v.w - __bfloat162float(h3));
    ((__nv_bfloat162*)H)[2*i]   = __nv_bfloat162(h0, h1);
    ((__nv_bfloat162*)H)[2*i+1] = __nv_bfloat162(h2, h3);
    ((__nv_bfloat162*)L)[2*i]   = __nv_bfloat162(l0, l1);
    ((__nv_bfloat162*)L)[2*i+1] = __nv_bfloat162(l2, l3);
}

// W[K,N] fp32 -> Th/Tl [N,K] bf16
__global__ __launch_bounds__(256) void transpose_split(
    const float* __restrict__ W, __nv_bfloat16* __restrict__ Th,
    __nv_bfloat16* __restrict__ Tl, int K, int N)
{
    __shared__ float ts[32][33];
    int k0 = blockIdx.y * 32, n0 = blockIdx.x * 32;
    int tx = threadIdx.x & 31, ty = threadIdx.x >> 5;
#pragma unroll
    for (int j = 0; j < 32; j += 8)
        ts[ty + j][tx] = W[(size_t)(k0 + ty + j) * N + n0 + tx];
    __syncthreads();
#pragma unroll
    for (int j = 0; j < 32; j += 8) {
        float v = ts[tx][ty + j];
        __nv_bfloat16 h = __float2bfloat16(v);
        __nv_bfloat16 l = __float2bfloat16(v - __bfloat162float(h));
        Th[(size_t)(n0 + ty + j) * K + k0 + tx] = h;
        Tl[(size_t)(n0 + ty + j) * K + k0 + tx] = l;
    }
}

// ================ mma.sync bf16 GEMM (3-term Markidis, fp32 accum) ================
// C[M,N] = (Ah+Al)[M,K] * (Bh+Bl)[N,K]^T
// CTA 128x128, BK=64, 256 threads (8 warps 2x4, warp tile 64x32), cp.async 2-stage.
#define GT_THREADS 256
#define ROWB 144                         // smem row stride bytes (64 bf16 + 16B pad)
#define TILEB (128 * ROWB)               // 18432 B per tile
#define STAGEB (4 * TILEB)               // Ah,Al,Bh,Bl = 73728 B
#define GT_SMEM_BYTES (2 * STAGEB)       // 147456 B

__global__ __launch_bounds__(GT_THREADS, 1) void gemm_tc(
    const __nv_bfloat16* __restrict__ Ah, const __nv_bfloat16* __restrict__ Al,
    const __nv_bfloat16* __restrict__ Bh, const __nv_bfloat16* __restrict__ Bl,
    float* __restrict__ C, int M, int N, int K)
{
    extern __shared__ char smc[];
    const uint32_t sb = smem_u32(smc);
    const int tid = threadIdx.x, wid = tid >> 5, lane = tid & 31;
    const int n0 = blockIdx.x * 128, m0 = blockIdx.y * 128;
    const int m_warp = (wid >> 2) * 64;      // 0 or 64
    const int n_warp = (wid & 3) * 32;       // 0,32,64,96

    float acc[4][4][4];
#pragma unroll
    for (int i = 0; i < 4; i++)
#pragma unroll
        for (int j = 0; j < 4; j++)
#pragma unroll
            for (int r = 0; r < 4; r++) acc[i][j][r] = 0.f;

    const int NC = K >> 6;   // 64-col chunks

    // --- async stage loader: 4096 16B chunks / 256 threads = 16 each
    auto issue_stage = [&](int kt, int stage) {
        const uint32_t base = sb + stage * STAGEB;
        const int kb = kt * 64;
#pragma unroll
        for (int it = 0; it < 16; it++) {
            int id = tid + it * 256;           // 0..4095
            int tile = id >> 10;               // 0:Ah 1:Al 2:Bh 3:Bl
            int cid = id & 1023;
            int row = cid >> 3;
            int ch  = cid & 7;
            uint32_t dst = base + tile * TILEB + row * ROWB + ch * 16;
            const __nv_bfloat16* src;
            if (tile == 0)      src = Ah + (size_t)(m0 + row) * K + kb + ch * 8;
            else if (tile == 1) src = Al + (size_t)(m0 + row) * K + kb + ch * 8;
            else if (tile == 2) src = Bh + (size_t)(n0 + row) * K + kb + ch * 8;
            else                src = Bl + (size_t)(n0 + row) * K + kb + ch * 8;
            CP_ASYNC16(dst, src);
        }
        CP_COMMIT();
    };

    issue_stage(0, 0);

    for (int kt = 0; kt < NC; kt++) {
        const int stage = kt & 1;
        if (kt + 1 < NC) {
            issue_stage(kt + 1, (kt + 1) & 1);
            CP_WAIT1();
        } else {
            CP_WAIT0();
        }
        __syncthreads();

        const uint32_t sA_h = sb + stage * STAGEB;
        const uint32_t sA_l = sA_h + TILEB;
        const uint32_t sB_h = sA_h + 2 * TILEB;
        const uint32_t sB_l = sA_h + 3 * TILEB;

        // ldmatrix address components
        const int a_row = m_warp + (lane & 15);
        const int b_row = n_warp + (lane & 7);

#pragma unroll
        for (int ks = 0; ks < 4; ks++) {
            const int k0 = ks * 16;
            const uint32_t a_cb = (uint32_t)((k0 + ((lane >> 4) << 3)) * 2);
            const uint32_t b_cb = (uint32_t)((k0 + (((lane >> 3) & 1) << 3)) * 2);

            uint32_t ah[4][4], al[4][4];
#pragma unroll
            for (int mt = 0; mt < 4; mt++) {
                uint32_t ra = (uint32_t)((a_row + mt * 16) * ROWB) + a_cb;
                LDMX4(ah[mt][0], ah[mt][1], ah[mt][2], ah[mt][3], sA_h + ra);
                LDMX4(al[mt][0], al[mt][1], al[mt][2], al[mt][3], sA_l + ra);
            }
            uint32_t bh[4][2], bl[4][2];
#pragma unroll
            for (int nt = 0; nt < 4; nt++) {
                uint32_t rb = (uint32_t)((b_row + nt * 8) * ROWB) + b_cb;
                LDMX2(bh[nt][0], bh[nt][1], sB_h + rb);
                LDMX2(bl[nt][0], bl[nt][1], sB_l + rb);
            }
#pragma unroll
            for (int mt = 0; mt < 4; mt++)
#pragma unroll
                for (int nt = 0; nt < 4; nt++) {
                    MMA16816(acc[mt][nt][0], acc[mt][nt][1], acc[mt][nt][2], acc[mt][nt][3],
                             ah[mt][0], ah[mt][1], ah[mt][2], ah[mt][3],
                             bh[nt][0], bh[nt][1]);
                    MMA16816(acc[mt][nt][0], acc[mt][nt][1], acc[mt][nt][2], acc[mt][nt][3],
                             ah[mt][0], ah[mt][1], ah[mt][2], ah[mt][3],
                             bl[nt][0], bl[nt][1]);
                    MMA16816(acc[mt][nt][0], acc[mt][nt][1], acc[mt][nt][2], acc[mt][nt][3],
                             al[mt][0], al[mt][1], al[mt][2], al[mt][3],
                             bh[nt][0], bh[nt][1]);
                }
        }
        __syncthreads();
    }

    // epilogue: c0,c1 -> C[m + lane/4][n + 2*(lane%4)], c2,c3 -> row+8
    const int lr = lane >> 2, lc = (lane & 3) << 1;
#pragma unroll
    for (int mt = 0; mt < 4; mt++) {
        const int mrow = m0 + m_warp + mt * 16 + lr;
#pragma unroll
        for (int nt = 0; nt < 4; nt++) {
            const int ncol = n0 + n_warp + nt * 8 + lc;
            *(float2*)(C + (size_t)mrow * N + ncol) =
                make_float2(acc[mt][nt][0], acc[mt][nt][1]);
            *(float2*)(C + (size_t)(mrow + 8) * N + ncol) =
                make_float2(acc[mt][nt][2], acc[mt][nt][3]);
        }
    }
}

// ---------------- RoPE on Q (in place) ----------------
__global__ __launch_bounds__(256) void rope_q_kernel(
    float* __restrict__ Q, const float* __restrict__ cosp, const float* __restrict__ sinp)
{
    const int t = blockIdx.x;
    float* row = Q + (size_t)t * (NH * HD);
    const float* cr = cosp + (size_t)t * HD;
    const float* sr = sinp + (size_t)t * HD;
    for (int i = threadIdx.x; i < NH * 64; i += 256) {
        int hh = i >> 6, d = i & 63;
        float* p = row + hh * HD;
        float x0 = p[d], x1 = p[d + 64];
        float c0 = cr[d], c1 = cr[d + 64];
        float s0 = sr[d], s1 = sr[d + 64];
        p[d]      = x0 * c0 - x1 * s0;
        p[d + 64] = x1 * c1 + x0 * s1;
    }
}

// ---------------- RoPE on K + transpose to [bkv][d][s] ----------------
__global__ __launch_bounds__(256) void rope_kt_kernel(
    const float* __restrict__ K, const float* __restrict__ cosp,
    const float* __restrict__ sinp, float* __restrict__ Kt)
{
    __shared__ float Ts[128 * 65];
    const int st = blockIdx.x, kvh = blockIdx.y, b = blockIdx.z;
    const int s0 = st * 64;
    const int tid = threadIdx.x;

    for (int i = tid; i < 64 * 64; i += 256) {
        int sl = i >> 6, d = i & 63;
        int t = b * SS + s0 + sl;
        const float* row = K + (size_t)t * (NKV * HD) + kvh * HD;
        float x0 = row[d], x1 = row[d + 64];
        float c0 = cosp[(size_t)t * HD + d], c1 = cosp[(size_t)t * HD + d + 64];
        float n0 = sinp[(size_t)t * HD + d], n1 = sinp[(size_t)t * HD + d + 64];
        Ts[d * 65 + sl]        = x0 * c0 - x1 * n0;
        Ts[(d + 64) * 65 + sl] = x1 * c1 + x0 * n1;
    }
    __syncthreads();
    float* base = Kt + ((size_t)(b * NKV + kvh)) * HD * SS + s0;
    for (int i = tid; i < 128 * 64; i += 256) {
        int d = i >> 6, sl = i & 63;
        base[(size_t)d * SS + sl] = Ts[d * 65 + sl];
    }
}

// ---------------- Flash attention (fp32, causal, online softmax) ----------------
#define FA_BQ 128
#define FA_BK 64
#define FA_THREADS 512
#define FA_SMEM_FLOATS (16384 + 8192 + 8192 + 8320 + 384 + 512)
#define FA_SMEM_BYTES (FA_SMEM_FLOATS * 4)

__global__ __launch_bounds__(FA_THREADS, 1) void flash_kernel(
    const float* __restrict__ Q, const float* __restrict__ Kt,
    const float* __restrict__ V, float* __restrict__ O)
{
    extern __shared__ float smf[];
    float* Qs   = smf;
    float* Ks   = Qs + 128 * 128;
    float* Vs   = Ks + 128 * 64;
    float* Ss   = Vs + 64 * 128;
    float* rowm = Ss + 128 * 65;
    float* rowl = rowm + 128;
    float* rsc  = rowl + 128;
    float* red  = rsc + 128;

    const int tid = threadIdx.x;
    const int qt = blockIdx.x, h = blockIdx.y, b = blockIdx.z;
    const int kvh = h >> 2;
    const int q0 = qt * FA_BQ;
    const int tx = tid & 15;
    const int ty = tid >> 4;

    const float* Qbase  = Q  + ((size_t)(b * SS + q0)) * (NH * HD) + h * HD;
    const float* Ktbase = Kt + ((size_t)(b * NKV + kvh)) * HD * SS;
    const float* Vbase  = V  + ((size_t)(b * SS)) * (NKV * HD) + kvh * HD;

    for (int i = tid; i < 128 * 32; i += FA_THREADS) {
        int r = i >> 5, c4 = (i & 31) << 2;
        *(float4*)&Qs[r * 128 + c4] = *(const float4*)(Qbase + (size_t)r * (NH * HD) + c4);
    }
    if (tid < 128) { rowm[tid] = -1e30f; rowl[tid] = 0.f; }

    float acc[4][8];
#pragma unroll
    for (int i = 0; i < 4; i++)
#pragma unroll
        for (int j = 0; j < 8; j++) acc[i][j] = 0.f;
    __syncthreads();

    const int ktiles = (q0 + FA_BQ) / FA_BK;
    for (int kt = 0; kt < ktiles; kt++) {
        const int k0 = kt * FA_BK;

        for (int i = tid; i < 128 * 16; i += FA_THREADS) {
            int d = i >> 4, c4 = (i & 15) << 2;
            *(float4*)&Ks[d * 64 + c4] = *(const float4*)(Ktbase + (size_t)d * SS + k0 + c4);
        }
        for (int i = tid; i < 64 * 32; i += FA_THREADS) {
            int r = i >> 5, c4 = (i & 31) << 2;
            *(float4*)&Vs[r * 128 + c4] = *(const float4*)(Vbase + (size_t)(k0 + r) * (NKV * HD) + c4);
        }
        __syncthreads();

        float sacc[4][4];
#pragma unroll
        for (int i = 0; i < 4; i++)
#pragma unroll
            for (int j = 0; j < 4; j++) sacc[i][j] = 0.f;

#pragma unroll 4
        for (int d = 0; d < 128; d++) {
            float4 kb = *(float4*)&Ks[d * 64 + (tx << 2)];
            float qa[4];
#pragma unroll
            for (int i = 0; i < 4; i++) qa[i] = Qs[(ty * 4 + i) * 128 + d];
#pragma unroll
            for (int i = 0; i < 4; i++) {
                sacc[i][0] += qa[i] * kb.x;
                sacc[i][1] += qa[i] * kb.y;
                sacc[i][2] += qa[i] * kb.z;
                sacc[i][3] += qa[i] * kb.w;
            }
        }

#pragma unroll
        for (int i = 0; i < 4; i++) {
            int qi = q0 + ty * 4 + i;
#pragma unroll
            for (int j = 0; j < 4; j++) {
                int kj = k0 + tx * 4 + j;
                float s = sacc[i][j] * SCALING;
                if (kj > qi) s = NEG_BIG;
                Ss[(ty * 4 + i) * 65 + tx * 4 + j] = s;
            }
        }
        __syncthreads();

        {
            const int r = tid & 127, seg = tid >> 7;
            float pm = -1e30f;
#pragma unroll
            for (int j = 0; j < 16; j++) pm = fmaxf(pm, Ss[r * 65 + seg * 16 + j]);
            red[seg * 128 + r] = pm;
            __syncthreads();
            float mo = rowm[r];
            float mt = fmaxf(fmaxf(red[r], red[128 + r]), fmaxf(red[256 + r], red[384 + r]));
            float mn = fmaxf(mo, mt);
            __syncthreads();
            float ps = 0.f;
#pragma unroll
            for (int j = 0; j < 16; j++) {
                float e = __expf(Ss[r * 65 + seg * 16 + j] - mn);
                Ss[r * 65 + seg * 16 + j] = e;
                ps += e;
            }
            red[seg * 128 + r] = ps;
            __syncthreads();
            if (seg == 0) {
                float l = red[r] + red[128 + r] + red[256 + r] + red[384 + r];
                float sc = __expf(mo - mn);
                rowl[r] = rowl[r] * sc + l;
                rowm[r] = mn;
                rsc[r]  = sc;
            }
            __syncthreads();
        }

        float f[4];
#pragma unroll
        for (int i = 0; i < 4; i++) f[i] = rsc[ty * 4 + i];
#pragma unroll
        for (int i = 0; i < 4; i++)
#pragma unroll
            for (int j = 0; j < 8; j++) acc[i][j] *= f[i];

#pragma unroll 2
        for (int k = 0; k < 64; k++) {
            float4 v0 = *(float4*)&Vs[k * 128 + tx * 8];
            float4 v1 = *(float4*)&Vs[k * 128 + tx * 8 + 4];
#pragma unroll
            for (int i = 0; i < 4; i++) {
                float p = Ss[(ty * 4 + i) * 65 + k];
                acc[i][0] += p * v0.x; acc[i][1] += p * v0.y;
                acc[i][2] += p * v0.z; acc[i][3] += p * v0.w;
                acc[i][4] += p * v1.x; acc[i][5] += p * v1.y;
                acc[i][6] += p * v1.z; acc[i][7] += p * v1.w;
            }
        }
        __syncthreads();
    }

    float* Ob = O + ((size_t)(b * SS + q0)) * (NH * HD) + h * HD;
#pragma unroll
    for (int i = 0; i < 4; i++) {
        float inv = 1.0f / rowl[ty * 4 + i];
        float4 o0 = make_float4(acc[i][0] * inv, acc[i][1] * inv, acc[i][2] * inv, acc[i][3] * inv);
        float4 o1 = make_float4(acc[i][4] * inv, acc[i][5] * inv, acc[i][6] * inv, acc[i][7] * inv);
        float* orow = Ob + (size_t)(ty * 4 + i) * (NH * HD) + tx * 8;
        *(float4*)(orow) = o0;
        *(float4*)(orow + 4) = o1;
    }
}

// ---------------- launch ----------------
extern "C" void kernel_launch(void* const* d_in, const int* in_sizes, int n_in,
                              void* d_out, int out_size)
{
    const float* hs   = (const float*)d_in[0];
    const float* cosp = (const float*)d_in[1];
    const float* sinp = (const float*)d_in[2];
    const float* wq = (const float*)d_in[4];
    const float* wk = (const float*)d_in[5];
    const float* wv = (const float*)d_in[6];
    const float* wo = (const float*)d_in[7];
    float* out = (float*)d_out;

    float *q, *k, *ktp, *v, *attn;
    __nv_bfloat16 *hsh, *hsl, *wqth, *wqtl, *wkth, *wktl, *wvth, *wvtl, *woth, *wotl, *ath, *atl;
    cudaGetSymbolAddress((void**)&q,    g_q);
    cudaGetSymbolAddress((void**)&k,    g_k);
    cudaGetSymbolAddress((void**)&ktp,  g_kt);
    cudaGetSymbolAddress((void**)&v,    g_v);
    cudaGetSymbolAddress((void**)&attn, g_attn);
    cudaGetSymbolAddress((void**)&hsh,  g_hs_h);
    cudaGetSymbolAddress((void**)&hsl,  g_hs_l);
    cudaGetSymbolAddress((void**)&wqth, g_wqt_h);
    cudaGetSymbolAddress((void**)&wqtl, g_wqt_l);
    cudaGetSymbolAddress((void**)&wkth, g_wkt_h);
    cudaGetSymbolAddress((void**)&wktl, g_wkt_l);
    cudaGetSymbolAddress((void**)&wvth, g_wvt_h);
    cudaGetSymbolAddress((void**)&wvtl, g_wvt_l);
    cudaGetSymbolAddress((void**)&woth, g_wot_h);
    cudaGetSymbolAddress((void**)&wotl, g_wot_l);
    cudaGetSymbolAddress((void**)&ath,  g_at_h);
    cudaGetSymbolAddress((void**)&atl,  g_at_l);

    cudaFuncSetAttribute(gemm_tc, cudaFuncAttributeMaxDynamicSharedMemorySize, GT_SMEM_BYTES);
    cudaFuncSetAttribute(flash_kernel, cudaFuncAttributeMaxDynamicSharedMemorySize, FA_SMEM_BYTES);

    // prep: split activations + transposed/split weights
    conv_split<<<(TOK * HID / 4 + 255) / 256, 256>>>(hs, hsh, hsl, TOK * HID / 4);
    transpose_split<<<dim3((NH*HD)/32, HID/32), 256>>>(wq, wqth, wqtl, HID, NH*HD);
    transpose_split<<<dim3((NKV*HD)/32, HID/32), 256>>>(wk, wkth, wktl, HID, NKV*HD);
    transpose_split<<<dim3((NKV*HD)/32, HID/32), 256>>>(wv, wvth, wvtl, HID, NKV*HD);
    transpose_split<<<dim3(HID/32, (NH*HD)/32), 256>>>(wo, woth, wotl, NH*HD, HID);

    // projections (mma.sync bf16 3-term)
    gemm_tc<<<dim3((NH*HD)/128, TOK/128), GT_THREADS, GT_SMEM_BYTES>>>(
        hsh, hsl, wqth, wqtl, q, TOK, NH*HD, HID);
    gemm_tc<<<dim3((NKV*HD)/128, TOK/128), GT_THREADS, GT_SMEM_BYTES>>>(
        hsh, hsl, wkth, wktl, k, TOK, NKV*HD, HID);
    gemm_tc<<<dim3((NKV*HD)/128, TOK/128), GT_THREADS, GT_SMEM_BYTES>>>(
        hsh, hsl, wvth, wvtl, v, TOK, NKV*HD, HID);

    // rope
    rope_q_kernel<<<TOK, 256>>>(q, cosp, sinp);
    rope_kt_kernel<<<dim3(SS / 64, NKV, BB), 256>>>(k, cosp, sinp, ktp);

    // attention (fp32)
    flash_kernel<<<dim3(SS / FA_BQ, NH, BB), FA_THREADS, FA_SMEM_BYTES>>>(q, ktp, v, attn);

    // output projection
    conv_split<<<(TOK * (NH*HD) / 4 + 255) / 256, 256>>>(attn, ath, atl, TOK * (NH*HD) / 4);
    gemm_tc<<<dim3(HID/128, TOK/128), GT_THREADS, GT_SMEM_BYTES>>>(
        ath, atl, woth, wotl, out, TOK, HID, HID);
}